// round 6
// baseline (speedup 1.0000x reference)
#include <cuda_runtime.h>
#include <math.h>

// Shape (2,3,128,128,128) fp32
#define NTOT   12582912
#define NROWS  98304          // 6*128*128 rows of 128 x-values
#define ALPHA  0.001
#define WPB    4
#define BLOCK  (WPB * 32)
#define GRID   (NROWS / WPB)  // 24576

__device__ double       g_acc[3];
__device__ unsigned int g_ticket;

// one warp per (vol,z,y) row; lane holds float4 (4 x-values)
__global__ __launch_bounds__(BLOCK, 6) void ace_main(
    const float* __restrict__ yp, const float* __restrict__ yt,
    float* __restrict__ out)
{
    const unsigned FULL = 0xFFFFFFFFu;
    const int wid  = threadIdx.x >> 5;
    const int lane = threadIdx.x & 31;
    const int r    = blockIdx.x * WPB + wid;

    const int y = r & 127;
    const int z = (r >> 7) & 127;
    const int ym_ = y > 0   ? y - 1 : 0;
    const int yq  = y < 127 ? y + 1 : 127;
    const int zm_ = z > 0   ? z - 1 : 0;
    const int zq  = z < 127 ? z + 1 : 127;

    const size_t vb = (size_t)(r >> 14) << 21;
    const float* U = yp + vb;

    #define RP(zz,yy) (((const float4*)(U + (((zz) << 14) + ((yy) << 7)))) + lane)
    const float4 c4  = __ldg(RP(z,   y ));
    const float4 zm4 = __ldg(RP(zm_, y ));
    const float4 zp4 = __ldg(RP(zq,  y ));
    const float4 ym4 = __ldg(RP(z,  ym_));
    const float4 yp4 = __ldg(RP(z,  yq ));
    const float4 mm4 = __ldg(RP(zm_, ym_));
    const float4 mp4 = __ldg(RP(zm_, yq ));
    const float4 pm4 = __ldg(RP(zq,  ym_));
    const float4 pp4 = __ldg(RP(zq,  yq ));
    const float4 t4  = __ldg(((const float4*)(yt + vb + ((z << 14) + (y << 7)))) + lane);
    #undef RP

    // collapse pairs immediately (frees source rows)
    const float ez4[4] = { zp4.x - zm4.x, zp4.y - zm4.y, zp4.z - zm4.z, zp4.w - zm4.w };
    const float sz [4] = { zp4.x + zm4.x, zp4.y + zm4.y, zp4.z + zm4.z, zp4.w + zm4.w };
    const float ey4[4] = { yp4.x - ym4.x, yp4.y - ym4.y, yp4.z - ym4.z, yp4.w - ym4.w };
    const float sy [4] = { yp4.x + ym4.x, yp4.y + ym4.y, yp4.z + ym4.z, yp4.w + ym4.w };
    const float gxy[4] = { (pp4.x - mp4.x) - (pm4.x - mm4.x),
                           (pp4.y - mp4.y) - (pm4.y - mm4.y),
                           (pp4.z - mp4.z) - (pm4.z - mm4.z),
                           (pp4.w - mp4.w) - (pm4.w - mm4.w) };
    const float tt [4] = { t4.x, t4.y, t4.z, t4.w };

    // 6-wide x-windows (clamped) for center row, ez, ey
    #define MK6(A, a0, a1, a2, a3)                                     \
        float A[6];                                                    \
        A[1] = a0; A[2] = a1; A[3] = a2; A[4] = a3;                    \
        {   float L = __shfl_up_sync(FULL, A[4], 1);                   \
            float R = __shfl_down_sync(FULL, A[1], 1);                 \
            A[0] = (lane == 0)  ? A[1] : L;                            \
            A[5] = (lane == 31) ? A[4] : R; }

    MK6(cc, c4.x,   c4.y,   c4.z,   c4.w)
    MK6(ez, ez4[0], ez4[1], ez4[2], ez4[3])
    MK6(ey, ey4[0], ey4[1], ey4[2], ey4[3])
    #undef MK6

    float ain = 0.f, aout = 0.f, ael = 0.f;

    #pragma unroll
    for (int j = 0; j < 4; j++) {
        const float uc = cc[j + 1];
        const float di = ez[j + 1];
        const float dj = ey[j + 1];
        const float dk = cc[j + 2] - cc[j];

        const float cii = fmaf(uc, -2.f, sz[j]);
        const float cjj = fmaf(uc, -2.f, sy[j]);
        const float ckk = fmaf(uc, -2.f, cc[j] + cc[j + 2]);
        const float lap = cii + cjj + ckk;

        const float Dik = ez[j + 2] - ez[j];
        const float Djk = ey[j + 2] - ey[j];
        const float Dij = gxy[j];

        const float di2 = di * di, dj2 = dj * dj, dk2 = dk * dk;
        const float S = di2 + dj2 + dk2;                 // = 4*(ci2+cj2+ck2)

        float acc = di2 * cii;
        acc = fmaf(dj2, cjj, acc);
        acc = fmaf(dk2, ckk, acc);
        acc = fmaf(Dik * Djk, Dij, acc);
        const float curv = fmaf(0.25f, fmaf(S, lap, -acc), lap);

        const float ee = fmaf(0.25f, S, 1e-8f);          // eps + s
        const float oo = fmaf(0.25f, S, 1.f);            // 1 + s  (~ (sqrt(1+s)+eps)^2)
        ael += __fdividef(curv * curv * sqrtf(ee), oo);

        const float t = tt[j];
        const float tm1 = t - 1.f;
        ain  = fmaf(uc, tm1 * tm1, ain);
        aout = fmaf(1.f - uc, t * t, aout);
    }

    // ---- block reduction ----
    #pragma unroll
    for (int o = 16; o > 0; o >>= 1) {
        ain  += __shfl_down_sync(FULL, ain,  o);
        aout += __shfl_down_sync(FULL, aout, o);
        ael  += __shfl_down_sync(FULL, ael,  o);
    }
    __shared__ float si[WPB], so[WPB], se[WPB];
    if (lane == 0) { si[wid] = ain; so[wid] = aout; se[wid] = ael; }
    __syncthreads();

    if (threadIdx.x == 0) {
        float A = si[0] + si[1] + si[2] + si[3];
        float B = so[0] + so[1] + so[2] + so[3];
        float E = se[0] + se[1] + se[2] + se[3];
        atomicAdd(&g_acc[0], (double)A);
        atomicAdd(&g_acc[1], (double)B);
        atomicAdd(&g_acc[2], (double)E);
        __threadfence();
        unsigned t = atomicAdd(&g_ticket, 1u);
        if (t == (unsigned)(GRID - 1)) {          // last block finalizes + resets
            __threadfence();
            double s0 = atomicAdd(&g_acc[0], 0.0);
            double s1 = atomicAdd(&g_acc[1], 0.0);
            double s2 = atomicAdd(&g_acc[2], 0.0);
            double res = fabs(s0) + fabs(s1) + s2 + ALPHA * (double)NTOT;
            out[0] = (float)res;
            g_acc[0] = 0.0; g_acc[1] = 0.0; g_acc[2] = 0.0;
            g_ticket = 0u;
        }
    }
}

extern "C" void kernel_launch(void* const* d_in, const int* in_sizes, int n_in,
                              void* d_out, int out_size) {
    const float* y_pred = (const float*)d_in[0];
    const float* y_true = (const float*)d_in[1];
    ace_main<<<GRID, BLOCK>>>(y_pred, y_true, (float*)d_out);
}

// round 7
// speedup vs baseline: 2.7675x; 2.7675x over previous
#include <cuda_runtime.h>
#include <math.h>

// Shape (2,3,128,128,128) fp32
#define NTOT   12582912
#define NGRP   24576          // 6*128*32 groups of 4 consecutive y-rows
#define ALPHA  0.001
#define WPB    4
#define BLOCK  (WPB * 32)
#define GRID   (NGRP / WPB)   // 6144

__device__ double       g_acc[3];
__device__ unsigned int g_ticket;

__device__ __forceinline__ float4 f4sub(float4 a, float4 b) {
    return make_float4(a.x - b.x, a.y - b.y, a.z - b.z, a.w - b.w);
}
__device__ __forceinline__ float4 f4add(float4 a, float4 b) {
    return make_float4(a.x + b.x, a.y + b.y, a.z + b.z, a.w + b.w);
}

// One warp per group of 4 consecutive y-rows (fixed vol,z); lane = float4 of x.
__global__ __launch_bounds__(BLOCK) void ace_main(
    const float* __restrict__ yp, const float* __restrict__ yt,
    float* __restrict__ out)
{
    const unsigned FULL = 0xFFFFFFFFu;
    const int wid  = threadIdx.x >> 5;
    const int lane = threadIdx.x & 31;
    const int g    = blockIdx.x * WPB + wid;

    const int y0  = (g & 31) << 2;          // first output row
    const int z   = (g >> 5) & 127;
    const int vol = g >> 12;
    const int zm_ = z > 0   ? z - 1 : 0;
    const int zq  = z < 127 ? z + 1 : 127;

    const float* U = yp + ((size_t)vol << 21);
    const float* T = yt + ((size_t)vol << 21);

    // levels l=0..5 cover y = y0-1 .. y0+4 (clamped)
    float4 cz[6], ez[6], sz[6];
    #pragma unroll
    for (int l = 0; l < 6; l++) {
        int yy = y0 - 1 + l;
        yy = yy < 0 ? 0 : (yy > 127 ? 127 : yy);
        const float4 a = __ldg(((const float4*)(U + ((zm_ << 14) + (yy << 7)))) + lane);
        const float4 b = __ldg(((const float4*)(U + ((zq  << 14) + (yy << 7)))) + lane);
        const float4 c = __ldg(((const float4*)(U + ((z   << 14) + (yy << 7)))) + lane);
        cz[l] = c;
        ez[l] = f4sub(b, a);                // u(z+1)-u(z-1) at this y-level
        sz[l] = f4add(b, a);                // u(z+1)+u(z-1)
    }
    float4 t4[4];
    #pragma unroll
    for (int j = 0; j < 4; j++)
        t4[j] = __ldg(((const float4*)(T + ((z << 14) + ((y0 + j) << 7)))) + lane);

    // 6-wide clamped x-window from a float4
    #define MK6(A, V)                                                  \
        float A[6];                                                    \
        A[1] = V.x; A[2] = V.y; A[3] = V.z; A[4] = V.w;                \
        {   float L_ = __shfl_up_sync(FULL, A[4], 1);                  \
            float R_ = __shfl_down_sync(FULL, A[1], 1);                \
            A[0] = (lane == 0)  ? A[1] : L_;                           \
            A[5] = (lane == 31) ? A[4] : R_; }

    float ain = 0.f, aout = 0.f, ael = 0.f;

    #pragma unroll
    for (int j = 0; j < 4; j++) {
        const int l = j + 1;
        const float4 eyv  = f4sub(cz[l + 1], cz[l - 1]);   // u(y+1)-u(y-1)
        const float4 syv  = f4add(cz[l + 1], cz[l - 1]);
        const float4 gxyv = f4sub(ez[l + 1], ez[l - 1]);   // mixed z,y
        const float4 szl  = sz[l];

        MK6(cc,  cz[l])
        MK6(ezw, ez[l])
        MK6(eyw, eyv)

        const float syA [4] = { syv.x,  syv.y,  syv.z,  syv.w  };
        const float szA [4] = { szl.x,  szl.y,  szl.z,  szl.w  };
        const float gxyA[4] = { gxyv.x, gxyv.y, gxyv.z, gxyv.w };
        const float ttA [4] = { t4[j].x, t4[j].y, t4[j].z, t4[j].w };

        #pragma unroll
        for (int k = 0; k < 4; k++) {
            const float uc = cc[k + 1];
            const float di = ezw[k + 1];
            const float dj = eyw[k + 1];
            const float dk = cc[k + 2] - cc[k];

            const float cii = fmaf(uc, -2.f, szA[k]);
            const float cjj = fmaf(uc, -2.f, syA[k]);
            const float ckk = fmaf(uc, -2.f, cc[k] + cc[k + 2]);
            const float lap = cii + cjj + ckk;

            const float Dik = ezw[k + 2] - ezw[k];
            const float Djk = eyw[k + 2] - eyw[k];
            const float Dij = gxyA[k];

            const float di2 = di * di, dj2 = dj * dj, dk2 = dk * dk;
            const float S = di2 + dj2 + dk2;             // = 4*(ci2+cj2+ck2)

            float acc = di2 * cii;
            acc = fmaf(dj2, cjj, acc);
            acc = fmaf(dk2, ckk, acc);
            acc = fmaf(Dik * Djk, Dij, acc);
            const float curv = fmaf(0.25f, fmaf(S, lap, -acc), lap);

            const float ee = fmaf(0.25f, S, 1e-8f);      // eps + s
            const float oo = fmaf(0.25f, S, 1.f);        // (sqrt(1+s)+eps)^2 ~ 1+s
            ael += __fdividef(curv * curv * sqrtf(ee), oo);

            const float t = ttA[k];
            const float tm1 = t - 1.f;
            ain  = fmaf(uc, tm1 * tm1, ain);
            aout = fmaf(1.f - uc, t * t, aout);
        }
    }
    #undef MK6

    // ---- block reduction ----
    #pragma unroll
    for (int o = 16; o > 0; o >>= 1) {
        ain  += __shfl_down_sync(FULL, ain,  o);
        aout += __shfl_down_sync(FULL, aout, o);
        ael  += __shfl_down_sync(FULL, ael,  o);
    }
    __shared__ float si[WPB], so[WPB], se[WPB];
    if (lane == 0) { si[wid] = ain; so[wid] = aout; se[wid] = ael; }
    __syncthreads();

    if (threadIdx.x == 0) {
        float A = si[0] + si[1] + si[2] + si[3];
        float B = so[0] + so[1] + so[2] + so[3];
        float E = se[0] + se[1] + se[2] + se[3];
        atomicAdd(&g_acc[0], (double)A);
        atomicAdd(&g_acc[1], (double)B);
        atomicAdd(&g_acc[2], (double)E);
        __threadfence();
        unsigned t = atomicAdd(&g_ticket, 1u);
        if (t == (unsigned)(GRID - 1)) {          // last block finalizes + resets
            __threadfence();
            double s0 = atomicAdd(&g_acc[0], 0.0);
            double s1 = atomicAdd(&g_acc[1], 0.0);
            double s2 = atomicAdd(&g_acc[2], 0.0);
            double res = fabs(s0) + fabs(s1) + s2 + ALPHA * (double)NTOT;
            out[0] = (float)res;
            g_acc[0] = 0.0; g_acc[1] = 0.0; g_acc[2] = 0.0;
            g_ticket = 0u;
        }
    }
}

extern "C" void kernel_launch(void* const* d_in, const int* in_sizes, int n_in,
                              void* d_out, int out_size) {
    const float* y_pred = (const float*)d_in[0];
    const float* y_true = (const float*)d_in[1];
    ace_main<<<GRID, BLOCK>>>(y_pred, y_true, (float*)d_out);
}